// round 13
// baseline (speedup 1.0000x reference)
#include <cuda_runtime.h>
#include <cuda_bf16.h>
#include <cstdint>
#include <cstddef>

// ---------------------------------------------------------------------------
// SimpleAttention B=4, N=4096, D=192.
// S = QK^T now on int8 IMMA (m16n8k32, 2-limb 15-bit fixed point, 3 products,
// exact int32 accumulation): half the MMA issues of the bf16 path.
// PV and projections remain bf16 mma.sync with 3-MMA split precision.
// d_out layout: [out (B*N*192) | weights (B*N*N)]
// Softmax without max-subtraction is exact-safe (|logit| <~ 33).
// ---------------------------------------------------------------------------

#define BATCH 4
#define NSEQ  4096
#define DDIM  192
#define NEGV  (-1e9f)
#define BND   (BATCH * NSEQ * DDIM)
#define WSZ   (DDIM * DDIM)

__device__ __align__(256) __nv_bfloat16 g_Ih[3 * BND];
__device__ __align__(256) __nv_bfloat16 g_Il[3 * BND];
__device__ __align__(256) __nv_bfloat16 g_Wh[3 * WSZ];
__device__ __align__(256) __nv_bfloat16 g_Wl[3 * WSZ];
// q/k as int8 limb planes + per-row scales; v as bf16 hi/lo planes
__device__ __align__(256) char g_Q8h[BND];
__device__ __align__(256) char g_Q8l[BND];
__device__ __align__(256) char g_K8h[BND];
__device__ __align__(256) char g_K8l[BND];
__device__ float g_QS[BATCH * NSEQ];
__device__ float g_KS[BATCH * NSEQ];
__device__ __align__(256) __nv_bfloat16 g_Vh[BND];
__device__ __align__(256) __nv_bfloat16 g_Vl[BND];
__device__ float g_Z[BATCH * NSEQ];

__device__ __forceinline__ void ld4(float* d, const float* s) {
    float4 t = *reinterpret_cast<const float4*>(s);
    d[0]=t.x; d[1]=t.y; d[2]=t.z; d[3]=t.w;
}
__device__ __forceinline__ void st4(float* d, const float* s) {
    float4 t; t.x=s[0]; t.y=s[1]; t.z=s[2]; t.w=s[3];
    *reinterpret_cast<float4*>(d) = t;
}
__device__ __forceinline__ void hl_split(float x, uint16_t& h, uint16_t& l) {
    __nv_bfloat16 hh = __float2bfloat16_rn(x);
    __nv_bfloat16 ll = __float2bfloat16_rn(x - __bfloat162float(hh));
    h = __bfloat16_as_ushort(hh); l = __bfloat16_as_ushort(ll);
}

#define CP_ASYNC16(dst, src) \
    asm volatile("cp.async.cg.shared.global [%0], [%1], 16;" :: "r"(dst), "l"(src) : "memory")
#define CP_COMMIT() asm volatile("cp.async.commit_group;" ::: "memory")
#define CP_WAIT0()  asm volatile("cp.async.wait_group 0;" ::: "memory")

__device__ __forceinline__ void ldsm4(uint32_t f[4], uint32_t addr) {
    asm volatile("ldmatrix.sync.aligned.m8n8.x4.shared.b16 {%0,%1,%2,%3}, [%4];\n"
        : "=r"(f[0]), "=r"(f[1]), "=r"(f[2]), "=r"(f[3]) : "r"(addr));
}
__device__ __forceinline__ void ldsm4t(uint32_t f[4], uint32_t addr) {
    asm volatile("ldmatrix.sync.aligned.m8n8.x4.trans.shared.b16 {%0,%1,%2,%3}, [%4];\n"
        : "=r"(f[0]), "=r"(f[1]), "=r"(f[2]), "=r"(f[3]) : "r"(addr));
}
__device__ __forceinline__ void mma_bf16(float c[4], const uint32_t a[4],
                                         uint32_t b0, uint32_t b1) {
    asm volatile(
        "mma.sync.aligned.m16n8k16.row.col.f32.bf16.bf16.f32 "
        "{%0,%1,%2,%3}, {%4,%5,%6,%7}, {%8,%9}, {%0,%1,%2,%3};\n"
        : "+f"(c[0]), "+f"(c[1]), "+f"(c[2]), "+f"(c[3])
        : "r"(a[0]), "r"(a[1]), "r"(a[2]), "r"(a[3]), "r"(b0), "r"(b1));
}
__device__ __forceinline__ void mma_s8(int c[4], const uint32_t a[4],
                                       uint32_t b0, uint32_t b1) {
    asm volatile(
        "mma.sync.aligned.m16n8k32.row.col.s32.s8.s8.s32 "
        "{%0,%1,%2,%3}, {%4,%5,%6,%7}, {%8,%9}, {%0,%1,%2,%3};\n"
        : "+r"(c[0]), "+r"(c[1]), "+r"(c[2]), "+r"(c[3])
        : "r"(a[0]), "r"(a[1]), "r"(a[2]), "r"(a[3]), "r"(b0), "r"(b1));
}

// bf16 tiles: 384B pitch, 24 16B-chunks
__device__ __forceinline__ uint32_t sw24(int r, int c) {
    return (uint32_t)(r * 384 + ((((c) & 24) | (((c) ^ (r)) & 7)) << 4));
}
// int8 tiles: 256B pitch, 12 used 16B-chunks
__device__ __forceinline__ uint32_t sw16(int r, int c) {
    return (uint32_t)(r * 256 + ((((c) & 8) | (((c) ^ (r)) & 7)) << 4));
}

// ---------------------------------------------------------------------------
// Kernel 0: convert inputs + weights to bf16 hi/lo planes.
// ---------------------------------------------------------------------------
__global__ void convert_kernel(const float* __restrict__ q,
                               const float* __restrict__ k,
                               const float* __restrict__ v,
                               const float* __restrict__ qw,
                               const float* __restrict__ kw,
                               const float* __restrict__ vw) {
    const int TOT4 = (3 * BND + 3 * WSZ) / 4;
    int i4 = blockIdx.x * blockDim.x + threadIdx.x;
    if (i4 >= TOT4) return;
    int idx = i4 * 4;
    const float* src; __nv_bfloat16* dh; __nv_bfloat16* dl;
    if (idx < 3 * BND) {
        int r = idx / BND, o = idx - r * BND;
        src = (r == 0 ? q : (r == 1 ? k : v)) + o;
        dh = g_Ih + r * BND + o; dl = g_Il + r * BND + o;
    } else {
        int wi = idx - 3 * BND;
        int r = wi / WSZ, o = wi - r * WSZ;
        src = (r == 0 ? qw : (r == 1 ? kw : vw)) + o;
        dh = g_Wh + r * WSZ + o; dl = g_Wl + r * WSZ + o;
    }
    float4 x = *reinterpret_cast<const float4*>(src);
    uint16_t h[4], l[4];
    hl_split(x.x, h[0], l[0]); hl_split(x.y, h[1], l[1]);
    hl_split(x.z, h[2], l[2]); hl_split(x.w, h[3], l[3]);
    *reinterpret_cast<uint2*>(dh) =
        make_uint2((uint32_t)h[0] | ((uint32_t)h[1] << 16),
                   (uint32_t)h[2] | ((uint32_t)h[3] << 16));
    *reinterpret_cast<uint2*>(dl) =
        make_uint2((uint32_t)l[0] | ((uint32_t)l[1] << 16),
                   (uint32_t)l[2] | ((uint32_t)l[3] << 16));
}

// ---------------------------------------------------------------------------
// Kernel 1: persistent projections via bf16 HMMA. Deferred epilogue:
// q/k -> int8 limb planes + per-row scale; v -> bf16 hi/lo planes.
// ---------------------------------------------------------------------------
#define PXH 0u
#define PXL 49152u
#define PWH 98304u
#define PWL 135168u
#define PSMEM 172032
#define NTILES 384

__global__ void __launch_bounds__(256, 1)
proj_kernel() {
    extern __shared__ char smem[];
    const uint32_t SB = (uint32_t)__cvta_generic_to_shared(smem);
    const int tid  = threadIdx.x;
    const int wid  = tid >> 5, lane = tid & 31;
    const int g = lane >> 2, t = lane & 3;
    const int q2 = lane >> 3, rI = lane & 7;
    const int rb = wid * 16;

    const int rowA = rb + (lane & 15);
    const int cAadd = lane >> 4;
    const int rowW = ((q2 >> 1) << 3) + rI;
    const int cWadd = q2 & 1;

    for (int tile = blockIdx.x; tile < NTILES; tile += gridDim.x) {
        const int mat   = tile >> 7;
        const int trow0 = (tile & 127) * 128;

        const __nv_bfloat16* Xh = g_Ih + (size_t)mat * BND + (size_t)trow0 * DDIM;
        const __nv_bfloat16* Xl = g_Il + (size_t)mat * BND + (size_t)trow0 * DDIM;
        const __nv_bfloat16* Wh = g_Wh + mat * WSZ;
        const __nv_bfloat16* Wl = g_Wl + mat * WSZ;

        // stage X (both planes) + W chunk 0
        for (int i = tid; i < 6144; i += 256) {
            int plane = i >= 3072;
            int ii = plane ? i - 3072 : i;
            int r = ii / 24, c = ii % 24;
            const __nv_bfloat16* src = (plane ? Xl : Xh) + (size_t)r * DDIM + c * 8;
            CP_ASYNC16(SB + (plane ? PXL : PXH) + sw24(r, c), src);
        }
        for (int i = tid; i < 4608; i += 256) {
            int plane = i >= 2304;
            int ii = plane ? i - 2304 : i;
            int r = ii / 24, c = ii % 24;
            const __nv_bfloat16* src = (plane ? Wl : Wh) + (size_t)r * DDIM + c * 8;
            CP_ASYNC16(SB + (plane ? PWL : PWH) + sw24(r, c), src);
        }
        CP_COMMIT(); CP_WAIT0(); __syncthreads();

        float c[2][12][4];
        #pragma unroll
        for (int cc = 0; cc < 2; cc++)
            #pragma unroll
            for (int ni = 0; ni < 12; ni++)
                #pragma unroll
                for (int j = 0; j < 4; j++) c[cc][ni][j] = 0.f;

        #pragma unroll
        for (int cc = 0; cc < 2; cc++) {
            #pragma unroll
            for (int d0 = 0; d0 < 192; d0 += 16) {
                const int ca = (d0 >> 3) + cAadd;
                const int cw = (d0 >> 3) + cWadd;
                uint32_t ah[4], al[4], wh[6][4], wl[6][4];
                ldsm4(ah, SB + PXH + sw24(rowA, ca));
                ldsm4(al, SB + PXL + sw24(rowA, ca));
                #pragma unroll
                for (int nb = 0; nb < 6; nb++) {
                    ldsm4(wh[nb], SB + PWH + sw24(nb * 16 + rowW, cw));
                    ldsm4(wl[nb], SB + PWL + sw24(nb * 16 + rowW, cw));
                }
                #pragma unroll
                for (int ni = 0; ni < 12; ni++) {
                    uint32_t b0h = wh[ni >> 1][(ni & 1) * 2], b1h = wh[ni >> 1][(ni & 1) * 2 + 1];
                    uint32_t b0l = wl[ni >> 1][(ni & 1) * 2], b1l = wl[ni >> 1][(ni & 1) * 2 + 1];
                    mma_bf16(c[cc][ni], ah, b0h, b1h);
                    mma_bf16(c[cc][ni], ah, b0l, b1l);
                    mma_bf16(c[cc][ni], al, b0h, b1h);
                }
            }
            __syncthreads();
            if (cc == 0) {   // stage W chunk 1
                for (int i = tid; i < 4608; i += 256) {
                    int plane = i >= 2304;
                    int ii = plane ? i - 2304 : i;
                    int r = ii / 24, ch = ii % 24;
                    const __nv_bfloat16* src = (plane ? Wl : Wh) + (size_t)(96 + r) * DDIM + ch * 8;
                    CP_ASYNC16(SB + (plane ? PWL : PWH) + sw24(r, ch), src);
                }
                CP_COMMIT(); CP_WAIT0(); __syncthreads();
            }
        }

        // ---- deferred epilogue ----
        if (mat == 2) {
            #pragma unroll
            for (int cc = 0; cc < 2; cc++)
                #pragma unroll
                for (int ni = 0; ni < 12; ni++)
                    #pragma unroll
                    for (int hf = 0; hf < 2; hf++) {
                        int row = trow0 + rb + g + hf * 8;
                        int col = cc * 96 + ni * 8 + 2 * t;
                        uint16_t h0, l0, h1, l1;
                        hl_split(c[cc][ni][hf * 2 + 0], h0, l0);
                        hl_split(c[cc][ni][hf * 2 + 1], h1, l1);
                        size_t idx = (size_t)row * DDIM + col;
                        *reinterpret_cast<uint32_t*>(&g_Vh[idx]) = (uint32_t)h0 | ((uint32_t)h1 << 16);
                        *reinterpret_cast<uint32_t*>(&g_Vl[idx]) = (uint32_t)l0 | ((uint32_t)l1 << 16);
                    }
        } else {
            float* QS = (mat == 0) ? g_QS : g_KS;
            char* Y8h = (mat == 0) ? g_Q8h : g_K8h;
            char* Y8l = (mat == 0) ? g_Q8l : g_K8l;

            float mx0 = 0.f, mx1 = 0.f;
            #pragma unroll
            for (int cc = 0; cc < 2; cc++)
                #pragma unroll
                for (int ni = 0; ni < 12; ni++) {
                    mx0 = fmaxf(mx0, fmaxf(fabsf(c[cc][ni][0]), fabsf(c[cc][ni][1])));
                    mx1 = fmaxf(mx1, fmaxf(fabsf(c[cc][ni][2]), fabsf(c[cc][ni][3])));
                }
            mx0 = fmaxf(mx0, __shfl_xor_sync(0xffffffffu, mx0, 1));
            mx0 = fmaxf(mx0, __shfl_xor_sync(0xffffffffu, mx0, 2));
            mx1 = fmaxf(mx1, __shfl_xor_sync(0xffffffffu, mx1, 1));
            mx1 = fmaxf(mx1, __shfl_xor_sync(0xffffffffu, mx1, 2));
            mx0 = fmaxf(mx0, 1e-20f); mx1 = fmaxf(mx1, 1e-20f);
            const float rs[2] = {32600.f / mx0, 32600.f / mx1};
            const int rw[2] = {trow0 + rb + g, trow0 + rb + g + 8};
            if (t == 0) {
                QS[rw[0]] = mx0 / 32600.f;
                QS[rw[1]] = mx1 / 32600.f;
            }
            #pragma unroll
            for (int cc = 0; cc < 2; cc++)
                #pragma unroll
                for (int ni = 0; ni < 12; ni++)
                    #pragma unroll
                    for (int hf = 0; hf < 2; hf++) {
                        int col = cc * 96 + ni * 8 + 2 * t;
                        int X0 = __float2int_rn(c[cc][ni][hf * 2 + 0] * rs[hf]);
                        int X1 = __float2int_rn(c[cc][ni][hf * 2 + 1] * rs[hf]);
                        int l0 = ((X0 + 128) & 255) - 128;
                        int h0 = (X0 - l0) >> 8;
                        int l1 = ((X1 + 128) & 255) - 128;
                        int h1 = (X1 - l1) >> 8;
                        size_t idx = (size_t)rw[hf] * DDIM + col;
                        *reinterpret_cast<uint16_t*>(Y8h + idx) =
                            (uint16_t)((h0 & 255) | ((h1 & 255) << 8));
                        *reinterpret_cast<uint16_t*>(Y8l + idx) =
                            (uint16_t)((l0 & 255) | ((l1 & 255) << 8));
                    }
        }
        __syncthreads();
    }
}

// ---------------------------------------------------------------------------
// Kernel 2: flash attention. S on int8 IMMA (2-limb), PV on bf16 HMMA.
// grid (32, 4), 256 threads; warp w owns q-rows 16w..16w+15.
// ---------------------------------------------------------------------------
#define Q8H 0u
#define Q8L 32768u
#define K8H 65536u
#define K8L 81920u
#define VHOF 98304u
#define VLOF 122880u
#define SKS  147456u
#define ZOF  147712u
#define ASMEM 148224

__global__ void __launch_bounds__(256, 1)
attn_kernel(const float* __restrict__ attn_mask,
            const float* __restrict__ bias,
            const float* __restrict__ o_w,
            float* __restrict__ out,
            float* __restrict__ wout) {
    extern __shared__ char smem[];
    const uint32_t SB = (uint32_t)__cvta_generic_to_shared(smem);
    float* zs  = reinterpret_cast<float*>(smem + ZOF);
    float* sks = reinterpret_cast<float*>(smem + SKS);

    const int b    = blockIdx.y;
    const int q0   = blockIdx.x * 128;
    const int tid  = threadIdx.x;
    const int wid  = tid >> 5, lane = tid & 31;
    const int g = lane >> 2, t = lane & 3;
    const int q2 = lane >> 3, rI = lane & 7;
    const int rb = wid * 16;

    const size_t bN = (size_t)b * NSEQ;

    // prologue: stage Q int8 planes + K(0) int8 planes + sk(0)
    for (int i = tid; i < 3072; i += 256) {
        int plane = i >= 1536;
        int ii = plane ? i - 1536 : i;
        int r = ii / 12, c = ii % 12;
        const char* src = (plane ? g_Q8l : g_Q8h) + (bN + q0 + r) * DDIM + c * 16;
        CP_ASYNC16(SB + (plane ? Q8L : Q8H) + sw16(r, c), src);
    }
    for (int i = tid; i < 1552; i += 256) {
        if (i < 768) {
            int r = i / 12, c = i % 12;
            CP_ASYNC16(SB + K8H + sw16(r, c), g_K8h + (bN + r) * DDIM + c * 16);
        } else if (i < 1536) {
            int ii = i - 768;
            int r = ii / 12, c = ii % 12;
            CP_ASYNC16(SB + K8L + sw16(r, c), g_K8l + (bN + r) * DDIM + c * 16);
        } else {
            int c2 = i - 1536;
            CP_ASYNC16(SB + SKS + c2 * 16, (const char*)(g_KS + bN + c2 * 4));
        }
    }
    CP_COMMIT();

    const int rowA  = rb + (lane & 15);
    const int cAadd = lane >> 4;
    const int rowK  = ((q2 >> 1) << 3) + rI;
    const int cKadd = q2 & 1;
    const int rVadd = ((q2 & 1) << 3) + rI;
    const int cVadd = q2 >> 1;

    // per-row q scales (x256 for limb weight)
    float dqs[2];
    dqs[0] = 256.f * g_QS[bN + q0 + rb + g];
    dqs[1] = 256.f * g_QS[bN + q0 + rb + g + 8];

    float o[24][4];
    #pragma unroll
    for (int ni = 0; ni < 24; ni++)
        #pragma unroll
        for (int j = 0; j < 4; j++) o[ni][j] = 0.f;
    float zacc[2] = {0.f, 0.f};

    for (int kt = 0; kt < 64; kt++) {
        const int k0 = kt * 64;
        CP_WAIT0();
        __syncthreads();

        // stage V(kt) bf16 planes
        for (int i = tid; i < 3072; i += 256) {
            int plane = i >= 1536;
            int ii = plane ? i - 1536 : i;
            int r = ii / 24, c = ii % 24;
            const __nv_bfloat16* src = (plane ? g_Vl : g_Vh) + (bN + k0 + r) * DDIM + c * 8;
            CP_ASYNC16(SB + (plane ? VLOF : VHOF) + sw24(r, c), src);
        }
        CP_COMMIT();

        // ---- S = Q @ K^T (int8, 2-limb) ----
        int sacc[8][4];
        #pragma unroll
        for (int ni = 0; ni < 8; ni++)
            #pragma unroll
            for (int j = 0; j < 4; j++) sacc[ni][j] = 0;

        // phase A: h*h
        #pragma unroll
        for (int s = 0; s < 6; s++) {
            uint32_t ah[4], kb[4][4];
            ldsm4(ah, SB + Q8H + sw16(rowA, 2 * s + cAadd));
            #pragma unroll
            for (int nb = 0; nb < 4; nb++)
                ldsm4(kb[nb], SB + K8H + sw16(nb * 16 + rowK, 2 * s + cKadd));
            #pragma unroll
            for (int ni = 0; ni < 8; ni++)
                mma_s8(sacc[ni], ah, kb[ni >> 1][(ni & 1) * 2], kb[ni >> 1][(ni & 1) * 2 + 1]);
        }
        #pragma unroll
        for (int ni = 0; ni < 8; ni++)
            #pragma unroll
            for (int j = 0; j < 4; j++) sacc[ni][j] <<= 8;
        // phase B: h*l + l*h
        #pragma unroll
        for (int s = 0; s < 6; s++) {
            uint32_t ah[4], al[4], kh2[4][4], kl2[4][4];
            ldsm4(ah, SB + Q8H + sw16(rowA, 2 * s + cAadd));
            ldsm4(al, SB + Q8L + sw16(rowA, 2 * s + cAadd));
            #pragma unroll
            for (int nb = 0; nb < 4; nb++) {
                ldsm4(kh2[nb], SB + K8H + sw16(nb * 16 + rowK, 2 * s + cKadd));
                ldsm4(kl2[nb], SB + K8L + sw16(nb * 16 + rowK, 2 * s + cKadd));
            }
            #pragma unroll
            for (int ni = 0; ni < 8; ni++) {
                mma_s8(sacc[ni], ah, kl2[ni >> 1][(ni & 1) * 2], kl2[ni >> 1][(ni & 1) * 2 + 1]);
                mma_s8(sacc[ni], al, kh2[ni >> 1][(ni & 1) * 2], kh2[ni >> 1][(ni & 1) * 2 + 1]);
            }
        }

        // ---- epilogue: rescale, exp -> wout + P fragments ----
        uint32_t ph[4][4], pl[4][4];
        #pragma unroll
        for (int ni = 0; ni < 8; ni++) {
            const int kk = ni >> 1, sub = ni & 1;
            const float dk0 = sks[ni * 8 + 2 * t];
            const float dk1 = sks[ni * 8 + 2 * t + 1];
            #pragma unroll
            for (int hf = 0; hf < 2; hf++) {
                const int rr = rb + g + hf * 8;
                const size_t off = (bN + q0 + rr) * (size_t)NSEQ + k0 + ni * 8 + 2 * t;
                float sf0 = (float)sacc[ni][hf * 2 + 0] * (dqs[hf] * dk0);
                float sf1 = (float)sacc[ni][hf * 2 + 1] * (dqs[hf] * dk1);
                float2 bb = *reinterpret_cast<const float2*>(&bias[off]);
                float2 mm = *reinterpret_cast<const float2*>(&attn_mask[off]);
                float p0 = __expf(sf0 + bb.x + mm.x * NEGV);
                float p1 = __expf(sf1 + bb.y + mm.y * NEGV);
                zacc[hf] += p0 + p1;
                *reinterpret_cast<float2*>(&wout[off]) = make_float2(p0, p1);
                uint16_t h0, l0, h1, l1;
                hl_split(p0, h0, l0); hl_split(p1, h1, l1);
                ph[kk][hf + sub * 2] = (uint32_t)h0 | ((uint32_t)h1 << 16);
                pl[kk][hf + sub * 2] = (uint32_t)l0 | ((uint32_t)l1 << 16);
            }
        }

        CP_WAIT0();
        __syncthreads();

        // stage K(kt+1) int8 planes + sk(kt+1)
        if (kt < 63) {
            const int kn = k0 + 64;
            for (int i = tid; i < 1552; i += 256) {
                if (i < 768) {
                    int r = i / 12, c = i % 12;
                    CP_ASYNC16(SB + K8H + sw16(r, c), g_K8h + (bN + kn + r) * DDIM + c * 16);
                } else if (i < 1536) {
                    int ii = i - 768;
                    int r = ii / 12, c = ii % 12;
                    CP_ASYNC16(SB + K8L + sw16(r, c), g_K8l + (bN + kn + r) * DDIM + c * 16);
                } else {
                    int c2 = i - 1536;
                    CP_ASYNC16(SB + SKS + c2 * 16, (const char*)(g_KS + bN + kn + c2 * 4));
                }
            }
            CP_COMMIT();
        }

        // ---- O += P @ V (bf16) ----
        #pragma unroll
        for (int nb = 0; nb < 12; nb++) {
            const int cV = cVadd + 2 * nb;
            #pragma unroll
            for (int kk = 0; kk < 4; kk++) {
                const int rV = kk * 16 + rVadd;
                uint32_t vh[4], vl[4];
                ldsm4t(vh, SB + VHOF + sw24(rV, cV));
                ldsm4t(vl, SB + VLOF + sw24(rV, cV));
                #pragma unroll
                for (int sub = 0; sub < 2; sub++) {
                    const int ni = 2 * nb + sub;
                    uint32_t b0h = vh[sub * 2], b1h = vh[sub * 2 + 1];
                    uint32_t b0l = vl[sub * 2], b1l = vl[sub * 2 + 1];
                    mma_bf16(o[ni], ph[kk], b0h, b1h);
                    mma_bf16(o[ni], ph[kk], b0l, b1l);
                    mma_bf16(o[ni], pl[kk], b0h, b1h);
                }
            }
        }
    }

    // ---- finalize Z ----
    {
        float v0 = zacc[0], v1 = zacc[1];
        v0 += __shfl_xor_sync(0xffffffffu, v0, 1);
        v0 += __shfl_xor_sync(0xffffffffu, v0, 2);
        v1 += __shfl_xor_sync(0xffffffffu, v1, 1);
        v1 += __shfl_xor_sync(0xffffffffu, v1, 2);
        if (t == 0) { zs[rb + g] = v0; zs[rb + g + 8] = v1; }
    }
    __syncthreads();
    if (tid < 128) g_Z[bN + q0 + tid] = zs[tid];

    // ---- normalized O -> smem fp32 (pitch 196; overwrites Q region) ----
    float* OF = reinterpret_cast<float*>(smem);
    #pragma unroll
    for (int hf = 0; hf < 2; hf++) {
        const int rr = rb + g + hf * 8;
        const float iz = 1.0f / zs[rr];
        #pragma unroll
        for (int ni = 0; ni < 24; ni++) {
            const int col = ni * 8 + 2 * t;
            OF[rr * 196 + col]     = o[ni][hf * 2 + 0] * iz;
            OF[rr * 196 + col + 1] = o[ni][hf * 2 + 1] * iz;
        }
    }
    __syncthreads();

    // ---- output projection (SIMT) ----
    {
        const int ty = tid >> 4, tx = tid & 15;
        float op[8][12];
        #pragma unroll
        for (int rr = 0; rr < 8; rr++)
            #pragma unroll
            for (int c = 0; c < 12; c++) op[rr][c] = 0.f;

        #pragma unroll 2
        for (int e4 = 0; e4 < 48; e4++) {
            float oa[8][4];
            #pragma unroll
            for (int rr = 0; rr < 8; rr++) ld4(oa[rr], &OF[(ty * 8 + rr) * 196 + e4 * 4]);
            float wv[12][4];
            #pragma unroll
            for (int c = 0; c < 12; c++) ld4(wv[c], &o_w[(size_t)(tx * 12 + c) * DDIM + e4 * 4]);
            #pragma unroll
            for (int dd = 0; dd < 4; dd++)
                #pragma unroll
                for (int rr = 0; rr < 8; rr++)
                    #pragma unroll
                    for (int c = 0; c < 12; c++)
                        op[rr][c] += oa[rr][dd] * wv[c][dd];
        }

        #pragma unroll
        for (int rr = 0; rr < 8; rr++) {
            size_t off = (bN + q0 + ty * 8 + rr) * (size_t)DDIM + tx * 12;
            st4(&out[off],     &op[rr][0]);
            st4(&out[off + 4], &op[rr][4]);
            st4(&out[off + 8], &op[rr][8]);
        }
    }
}

// ---------------------------------------------------------------------------
// Kernel 3: normalize weights in place.
// ---------------------------------------------------------------------------
__global__ void norm_kernel(float* __restrict__ wout) {
    const int row = blockIdx.x;
    const float inv = 1.0f / g_Z[row];
    float4* p = reinterpret_cast<float4*>(wout) + (size_t)row * (NSEQ / 4);
    const int t = threadIdx.x;
    #pragma unroll
    for (int j = 0; j < 4; j++) {
        float4 v = p[t + j * 256];
        v.x *= inv; v.y *= inv; v.z *= inv; v.w *= inv;
        p[t + j * 256] = v;
    }
}

// ---------------------------------------------------------------------------
extern "C" void kernel_launch(void* const* d_in, const int* in_sizes, int n_in,
                              void* d_out, int out_size) {
    const float* query = (const float*)d_in[0];
    const float* key_t = (const float*)d_in[1];
    const float* value = (const float*)d_in[2];
    const float* mask  = (const float*)d_in[3];
    const float* bias  = (const float*)d_in[4];
    const float* q_w   = (const float*)d_in[5];
    const float* k_w   = (const float*)d_in[6];
    const float* v_w   = (const float*)d_in[7];
    const float* o_w   = (const float*)d_in[8];

    float* out  = (float*)d_out;
    float* wout = (float*)d_out + (size_t)BATCH * NSEQ * DDIM;

    cudaFuncSetAttribute(proj_kernel, cudaFuncAttributeMaxDynamicSharedMemorySize, PSMEM);
    cudaFuncSetAttribute(attn_kernel, cudaFuncAttributeMaxDynamicSharedMemorySize, ASMEM);

    const int TOT4 = (3 * BND + 3 * WSZ) / 4;
    convert_kernel<<<(TOT4 + 255) / 256, 256>>>(query, key_t, value, q_w, k_w, v_w);

    proj_kernel<<<148, 256, PSMEM>>>();

    dim3 agrid(NSEQ / 128, BATCH);
    attn_kernel<<<agrid, 256, ASMEM>>>(mask, bias, o_w, out, wout);

    norm_kernel<<<BATCH * NSEQ, 256>>>(wout);
}

// round 15
// speedup vs baseline: 2.3113x; 2.3113x over previous
#include <cuda_runtime.h>
#include <cuda_bf16.h>
#include <cstdint>
#include <cstddef>

// ---------------------------------------------------------------------------
// SimpleAttention B=4, N=4096, D=192 — all GEMMs on mma.sync bf16 with 3-MMA
// split precision. Projections: convert -> persistent HMMA kernel (148 CTAs).
// Attention: warp-owns-16-rows layout, P in registers (at the mma.sync issue
// floor). Separate norm kernel at DRAM roofline with explicit load batching.
// d_out layout: [out (B*N*192) | weights (B*N*N)]
// Softmax without max-subtraction is exact-safe (|logit| <~ 33).
// ---------------------------------------------------------------------------

#define BATCH 4
#define NSEQ  4096
#define DDIM  192
#define NEGV  (-1e9f)
#define BND   (BATCH * NSEQ * DDIM)
#define WSZ   (DDIM * DDIM)

__device__ __align__(256) __nv_bfloat16 g_Ih[3 * BND];
__device__ __align__(256) __nv_bfloat16 g_Il[3 * BND];
__device__ __align__(256) __nv_bfloat16 g_Wh[3 * WSZ];
__device__ __align__(256) __nv_bfloat16 g_Wl[3 * WSZ];
__device__ __align__(256) __nv_bfloat16 g_Qh[BND];
__device__ __align__(256) __nv_bfloat16 g_Ql[BND];
__device__ __align__(256) __nv_bfloat16 g_Kh[BND];
__device__ __align__(256) __nv_bfloat16 g_Kl[BND];
__device__ __align__(256) __nv_bfloat16 g_Vh[BND];
__device__ __align__(256) __nv_bfloat16 g_Vl[BND];
__device__ float g_Z[BATCH * NSEQ];

__device__ __forceinline__ void ld4(float* d, const float* s) {
    float4 t = *reinterpret_cast<const float4*>(s);
    d[0]=t.x; d[1]=t.y; d[2]=t.z; d[3]=t.w;
}
__device__ __forceinline__ void st4(float* d, const float* s) {
    float4 t; t.x=s[0]; t.y=s[1]; t.z=s[2]; t.w=s[3];
    *reinterpret_cast<float4*>(d) = t;
}
__device__ __forceinline__ void hl_split(float x, uint16_t& h, uint16_t& l) {
    __nv_bfloat16 hh = __float2bfloat16_rn(x);
    __nv_bfloat16 ll = __float2bfloat16_rn(x - __bfloat162float(hh));
    h = __bfloat16_as_ushort(hh); l = __bfloat16_as_ushort(ll);
}

#define CP_ASYNC16(dst, src) \
    asm volatile("cp.async.cg.shared.global [%0], [%1], 16;" :: "r"(dst), "l"(src) : "memory")
#define CP_COMMIT() asm volatile("cp.async.commit_group;" ::: "memory")
#define CP_WAIT0()  asm volatile("cp.async.wait_group 0;" ::: "memory")

__device__ __forceinline__ void ldsm4(uint32_t f[4], uint32_t addr) {
    asm volatile("ldmatrix.sync.aligned.m8n8.x4.shared.b16 {%0,%1,%2,%3}, [%4];\n"
        : "=r"(f[0]), "=r"(f[1]), "=r"(f[2]), "=r"(f[3]) : "r"(addr));
}
__device__ __forceinline__ void ldsm4t(uint32_t f[4], uint32_t addr) {
    asm volatile("ldmatrix.sync.aligned.m8n8.x4.trans.shared.b16 {%0,%1,%2,%3}, [%4];\n"
        : "=r"(f[0]), "=r"(f[1]), "=r"(f[2]), "=r"(f[3]) : "r"(addr));
}
__device__ __forceinline__ void mma_bf16(float c[4], const uint32_t a[4],
                                         uint32_t b0, uint32_t b1) {
    asm volatile(
        "mma.sync.aligned.m16n8k16.row.col.f32.bf16.bf16.f32 "
        "{%0,%1,%2,%3}, {%4,%5,%6,%7}, {%8,%9}, {%0,%1,%2,%3};\n"
        : "+f"(c[0]), "+f"(c[1]), "+f"(c[2]), "+f"(c[3])
        : "r"(a[0]), "r"(a[1]), "r"(a[2]), "r"(a[3]), "r"(b0), "r"(b1));
}

__device__ __forceinline__ uint32_t sw24(int r, int c) {
    return (uint32_t)(r * 384 + ((((c) & 24) | (((c) ^ (r)) & 7)) << 4));
}

// ---------------------------------------------------------------------------
// Kernel 0: convert inputs + weights to bf16 hi/lo planes. 8 elems/thread.
// ---------------------------------------------------------------------------
__global__ void convert_kernel(const float* __restrict__ q,
                               const float* __restrict__ k,
                               const float* __restrict__ v,
                               const float* __restrict__ qw,
                               const float* __restrict__ kw,
                               const float* __restrict__ vw) {
    const int TOT8 = (3 * BND + 3 * WSZ) / 8;
    int i8 = blockIdx.x * blockDim.x + threadIdx.x;
    if (i8 >= TOT8) return;
    int idx = i8 * 8;
    const float* src; __nv_bfloat16* dh; __nv_bfloat16* dl;
    if (idx < 3 * BND) {
        int r = idx / BND, o = idx - r * BND;
        src = (r == 0 ? q : (r == 1 ? k : v)) + o;
        dh = g_Ih + r * BND + o; dl = g_Il + r * BND + o;
    } else {
        int wi = idx - 3 * BND;
        int r = wi / WSZ, o = wi - r * WSZ;
        src = (r == 0 ? qw : (r == 1 ? kw : vw)) + o;
        dh = g_Wh + r * WSZ + o; dl = g_Wl + r * WSZ + o;
    }
    float4 x0 = *reinterpret_cast<const float4*>(src);
    float4 x1 = *reinterpret_cast<const float4*>(src + 4);
    uint16_t h[8], l[8];
    hl_split(x0.x, h[0], l[0]); hl_split(x0.y, h[1], l[1]);
    hl_split(x0.z, h[2], l[2]); hl_split(x0.w, h[3], l[3]);
    hl_split(x1.x, h[4], l[4]); hl_split(x1.y, h[5], l[5]);
    hl_split(x1.z, h[6], l[6]); hl_split(x1.w, h[7], l[7]);
    uint4 ph, pl;
    ph.x = (uint32_t)h[0] | ((uint32_t)h[1] << 16);
    ph.y = (uint32_t)h[2] | ((uint32_t)h[3] << 16);
    ph.z = (uint32_t)h[4] | ((uint32_t)h[5] << 16);
    ph.w = (uint32_t)h[6] | ((uint32_t)h[7] << 16);
    pl.x = (uint32_t)l[0] | ((uint32_t)l[1] << 16);
    pl.y = (uint32_t)l[2] | ((uint32_t)l[3] << 16);
    pl.z = (uint32_t)l[4] | ((uint32_t)l[5] << 16);
    pl.w = (uint32_t)l[6] | ((uint32_t)l[7] << 16);
    *reinterpret_cast<uint4*>(dh) = ph;
    *reinterpret_cast<uint4*>(dl) = pl;
}

// ---------------------------------------------------------------------------
// Kernel 1: persistent projections via HMMA. grid 148, each CTA loops tiles.
// ---------------------------------------------------------------------------
#define PXH 0u
#define PXL 49152u
#define PWH 98304u
#define PWL 135168u
#define PSMEM 172032
#define NTILES 384

__global__ void __launch_bounds__(256, 1)
proj_kernel() {
    extern __shared__ char smem[];
    const uint32_t SB = (uint32_t)__cvta_generic_to_shared(smem);
    const int tid  = threadIdx.x;
    const int wid  = tid >> 5, lane = tid & 31;
    const int g = lane >> 2, t = lane & 3;
    const int q2 = lane >> 3, rI = lane & 7;
    const int rb = wid * 16;

    const int rowA = rb + (lane & 15);
    const int cAadd = lane >> 4;
    const int rowW = ((q2 >> 1) << 3) + rI;
    const int cWadd = q2 & 1;

    for (int tile = blockIdx.x; tile < NTILES; tile += gridDim.x) {
        const int mat  = tile >> 7;
        const int row0 = (tile & 127) * 128;

        const __nv_bfloat16* Xh = g_Ih + (size_t)mat * BND + (size_t)row0 * DDIM;
        const __nv_bfloat16* Xl = g_Il + (size_t)mat * BND + (size_t)row0 * DDIM;
        const __nv_bfloat16* Wh = g_Wh + mat * WSZ;
        const __nv_bfloat16* Wl = g_Wl + mat * WSZ;
        __nv_bfloat16* Yh = (mat == 0 ? g_Qh : (mat == 1 ? g_Kh : g_Vh));
        __nv_bfloat16* Yl = (mat == 0 ? g_Ql : (mat == 1 ? g_Kl : g_Vl));

        for (int i = tid; i < 6144; i += 256) {
            int plane = i >= 3072;
            int ii = plane ? i - 3072 : i;
            int r = ii / 24, c = ii % 24;
            const __nv_bfloat16* src = (plane ? Xl : Xh) + (size_t)r * DDIM + c * 8;
            CP_ASYNC16(SB + (plane ? PXL : PXH) + sw24(r, c), src);
        }
        for (int i = tid; i < 4608; i += 256) {
            int plane = i >= 2304;
            int ii = plane ? i - 2304 : i;
            int r = ii / 24, c = ii % 24;
            const __nv_bfloat16* src = (plane ? Wl : Wh) + (size_t)r * DDIM + c * 8;
            CP_ASYNC16(SB + (plane ? PWL : PWH) + sw24(r, c), src);
        }
        CP_COMMIT(); CP_WAIT0(); __syncthreads();

        for (int cc = 0; cc < 2; cc++) {
            float c[12][4];
            #pragma unroll
            for (int ni = 0; ni < 12; ni++)
                #pragma unroll
                for (int j = 0; j < 4; j++) c[ni][j] = 0.f;

            #pragma unroll
            for (int d0 = 0; d0 < 192; d0 += 16) {
                const int ca = (d0 >> 3) + cAadd;
                const int cw = (d0 >> 3) + cWadd;
                uint32_t ah[4], al[4], wh[6][4], wl[6][4];
                ldsm4(ah, SB + PXH + sw24(rowA, ca));
                ldsm4(al, SB + PXL + sw24(rowA, ca));
                #pragma unroll
                for (int nb = 0; nb < 6; nb++) {
                    ldsm4(wh[nb], SB + PWH + sw24(nb * 16 + rowW, cw));
                    ldsm4(wl[nb], SB + PWL + sw24(nb * 16 + rowW, cw));
                }
                #pragma unroll
                for (int ni = 0; ni < 12; ni++) {
                    uint32_t b0h = wh[ni >> 1][(ni & 1) * 2], b1h = wh[ni >> 1][(ni & 1) * 2 + 1];
                    uint32_t b0l = wl[ni >> 1][(ni & 1) * 2], b1l = wl[ni >> 1][(ni & 1) * 2 + 1];
                    mma_bf16(c[ni], ah, b0h, b1h);
                    mma_bf16(c[ni], ah, b0l, b1l);
                    mma_bf16(c[ni], al, b0h, b1h);
                }
            }
            __syncthreads();
            if (cc == 0) {
                for (int i = tid; i < 4608; i += 256) {
                    int plane = i >= 2304;
                    int ii = plane ? i - 2304 : i;
                    int r = ii / 24, ch = ii % 24;
                    const __nv_bfloat16* src = (plane ? Wl : Wh) + (size_t)(96 + r) * DDIM + ch * 8;
                    CP_ASYNC16(SB + (plane ? PWL : PWH) + sw24(r, ch), src);
                }
                CP_COMMIT();
            }
            #pragma unroll
            for (int ni = 0; ni < 12; ni++) {
                #pragma unroll
                for (int hf = 0; hf < 2; hf++) {
                    int row = row0 + rb + g + hf * 8;
                    int col = cc * 96 + ni * 8 + 2 * t;
                    uint16_t h0, l0, h1, l1;
                    hl_split(c[ni][hf * 2 + 0], h0, l0);
                    hl_split(c[ni][hf * 2 + 1], h1, l1);
                    size_t idx = (size_t)row * DDIM + col;
                    *reinterpret_cast<uint32_t*>(&Yh[idx]) = (uint32_t)h0 | ((uint32_t)h1 << 16);
                    *reinterpret_cast<uint32_t*>(&Yl[idx]) = (uint32_t)l0 | ((uint32_t)l1 << 16);
                }
            }
            if (cc == 0) { CP_WAIT0(); __syncthreads(); }
        }
        __syncthreads();
    }
}

// ---------------------------------------------------------------------------
// Kernel 2: HMMA flash attention (R9/R12 structure), P in registers.
// grid (32, 4), 256 threads; warp w owns q-rows 16w..16w+15.
// ---------------------------------------------------------------------------
#define QHOF 0u
#define QLOF 49152u
#define KHOF 98304u
#define KLOF 122880u
#define VHOF 147456u
#define VLOF 172032u
#define ZOF  196608u
#define ASMEM 197120

__global__ void __launch_bounds__(256, 1)
attn_kernel(const float* __restrict__ attn_mask,
            const float* __restrict__ bias,
            const float* __restrict__ o_w,
            float* __restrict__ out,
            float* __restrict__ wout) {
    extern __shared__ char smem[];
    const uint32_t SB = (uint32_t)__cvta_generic_to_shared(smem);
    float* zs = reinterpret_cast<float*>(smem + ZOF);

    const int b    = blockIdx.y;
    const int q0   = blockIdx.x * 128;
    const int tid  = threadIdx.x;
    const int wid  = tid >> 5, lane = tid & 31;
    const int g = lane >> 2, t = lane & 3;
    const int q2 = lane >> 3, rI = lane & 7;
    const int rb = wid * 16;

    const size_t bN = (size_t)b * NSEQ;
    const size_t qoff = (bN + q0) * DDIM;

    for (int i = tid; i < 6144; i += 256) {
        int plane = i >= 3072;
        int ii = plane ? i - 3072 : i;
        int r = ii / 24, c = ii % 24;
        const __nv_bfloat16* src = (plane ? g_Ql : g_Qh) + qoff + (size_t)r * DDIM + c * 8;
        CP_ASYNC16(SB + (plane ? QLOF : QHOF) + sw24(r, c), src);
    }
    for (int i = tid; i < 3072; i += 256) {
        int plane = i >= 1536;
        int ii = plane ? i - 1536 : i;
        int r = ii / 24, c = ii % 24;
        const __nv_bfloat16* src = (plane ? g_Kl : g_Kh) + (bN + r) * DDIM + c * 8;
        CP_ASYNC16(SB + (plane ? KLOF : KHOF) + sw24(r, c), src);
    }
    CP_COMMIT();

    const int rowA  = rb + (lane & 15);
    const int cAadd = lane >> 4;
    const int rowK  = ((q2 >> 1) << 3) + rI;
    const int cKadd = q2 & 1;
    const int rVadd = ((q2 & 1) << 3) + rI;
    const int cVadd = q2 >> 1;

    float o[24][4];
    #pragma unroll
    for (int ni = 0; ni < 24; ni++)
        #pragma unroll
        for (int j = 0; j < 4; j++) o[ni][j] = 0.f;
    float zacc[2] = {0.f, 0.f};

    for (int kt = 0; kt < 64; kt++) {
        const int k0 = kt * 64;
        CP_WAIT0();
        __syncthreads();

        for (int i = tid; i < 3072; i += 256) {
            int plane = i >= 1536;
            int ii = plane ? i - 1536 : i;
            int r = ii / 24, c = ii % 24;
            const __nv_bfloat16* src = (plane ? g_Vl : g_Vh) + (bN + k0 + r) * DDIM + c * 8;
            CP_ASYNC16(SB + (plane ? VLOF : VHOF) + sw24(r, c), src);
        }
        CP_COMMIT();

        // ---- S = Q @ K^T ----
        float s[8][4];
        #pragma unroll
        for (int ni = 0; ni < 8; ni++)
            #pragma unroll
            for (int j = 0; j < 4; j++) s[ni][j] = 0.f;

        #pragma unroll
        for (int d0 = 0; d0 < 192; d0 += 16) {
            const int ca = (d0 >> 3) + cAadd;
            const int ck = (d0 >> 3) + cKadd;
            uint32_t ah[4], al[4], kh[4][4], kl[4][4];
            ldsm4(ah, SB + QHOF + sw24(rowA, ca));
            ldsm4(al, SB + QLOF + sw24(rowA, ca));
            #pragma unroll
            for (int nb = 0; nb < 4; nb++) {
                ldsm4(kh[nb], SB + KHOF + sw24(nb * 16 + rowK, ck));
                ldsm4(kl[nb], SB + KLOF + sw24(nb * 16 + rowK, ck));
            }
            #pragma unroll
            for (int ni = 0; ni < 8; ni++) {
                uint32_t b0h = kh[ni >> 1][(ni & 1) * 2], b1h = kh[ni >> 1][(ni & 1) * 2 + 1];
                uint32_t b0l = kl[ni >> 1][(ni & 1) * 2], b1l = kl[ni >> 1][(ni & 1) * 2 + 1];
                mma_bf16(s[ni], ah, b0h, b1h);
                mma_bf16(s[ni], ah, b0l, b1l);
                mma_bf16(s[ni], al, b0h, b1h);
            }
        }

        // ---- epilogue: exp -> wout + P fragments in registers ----
        uint32_t ph[4][4], pl[4][4];
        #pragma unroll
        for (int ni = 0; ni < 8; ni++) {
            const int kk = ni >> 1, sub = ni & 1;
            #pragma unroll
            for (int hf = 0; hf < 2; hf++) {
                const int rr = rb + g + hf * 8;
                const size_t off = (bN + q0 + rr) * (size_t)NSEQ + k0 + ni * 8 + 2 * t;
                float2 bb = *reinterpret_cast<const float2*>(&bias[off]);
                float2 mm = *reinterpret_cast<const float2*>(&attn_mask[off]);
                float p0 = __expf(s[ni][hf * 2 + 0] + bb.x + mm.x * NEGV);
                float p1 = __expf(s[ni][hf * 2 + 1] + bb.y + mm.y * NEGV);
                zacc[hf] += p0 + p1;
                *reinterpret_cast<float2*>(&wout[off]) = make_float2(p0, p1);
                uint16_t h0, l0, h1, l1;
                hl_split(p0, h0, l0); hl_split(p1, h1, l1);
                ph[kk][hf + sub * 2] = (uint32_t)h0 | ((uint32_t)h1 << 16);
                pl[kk][hf + sub * 2] = (uint32_t)l0 | ((uint32_t)l1 << 16);
            }
        }

        CP_WAIT0();
        __syncthreads();

        if (kt < 63) {
            const int kn = k0 + 64;
            for (int i = tid; i < 3072; i += 256) {
                int plane = i >= 1536;
                int ii = plane ? i - 1536 : i;
                int r = ii / 24, c = ii % 24;
                const __nv_bfloat16* src = (plane ? g_Kl : g_Kh) + (bN + kn + r) * DDIM + c * 8;
                CP_ASYNC16(SB + (plane ? KLOF : KHOF) + sw24(r, c), src);
            }
            CP_COMMIT();
        }

        // ---- O += P @ V ----
        #pragma unroll
        for (int nb = 0; nb < 12; nb++) {
            const int cV = cVadd + 2 * nb;
            #pragma unroll
            for (int kk = 0; kk < 4; kk++) {
                const int rV = kk * 16 + rVadd;
                uint32_t vh[4], vl[4];
                ldsm4t(vh, SB + VHOF + sw24(rV, cV));
                ldsm4t(vl, SB + VLOF + sw24(rV, cV));
                #pragma unroll
                for (int sub = 0; sub < 2; sub++) {
                    const int ni = 2 * nb + sub;
                    uint32_t b0h = vh[sub * 2], b1h = vh[sub * 2 + 1];
                    uint32_t b0l = vl[sub * 2], b1l = vl[sub * 2 + 1];
                    mma_bf16(o[ni], ph[kk], b0h, b1h);
                    mma_bf16(o[ni], ph[kk], b0l, b1l);
                    mma_bf16(o[ni], pl[kk], b0h, b1h);
                }
            }
        }
    }

    // ---- finalize Z ----
    {
        float v0 = zacc[0], v1 = zacc[1];
        v0 += __shfl_xor_sync(0xffffffffu, v0, 1);
        v0 += __shfl_xor_sync(0xffffffffu, v0, 2);
        v1 += __shfl_xor_sync(0xffffffffu, v1, 1);
        v1 += __shfl_xor_sync(0xffffffffu, v1, 2);
        if (t == 0) { zs[rb + g] = v0; zs[rb + g + 8] = v1; }
    }
    __syncthreads();
    if (tid < 128) g_Z[bN + q0 + tid] = zs[tid];

    // ---- normalized O -> smem fp32 ----
    float* OF = reinterpret_cast<float*>(smem);
    #pragma unroll
    for (int hf = 0; hf < 2; hf++) {
        const int rr = rb + g + hf * 8;
        const float iz = 1.0f / zs[rr];
        #pragma unroll
        for (int ni = 0; ni < 24; ni++) {
            const int col = ni * 8 + 2 * t;
            OF[rr * 196 + col]     = o[ni][hf * 2 + 0] * iz;
            OF[rr * 196 + col + 1] = o[ni][hf * 2 + 1] * iz;
        }
    }
    __syncthreads();

    // ---- output projection (SIMT) ----
    {
        const int ty = tid >> 4, tx = tid & 15;
        float op[8][12];
        #pragma unroll
        for (int rr = 0; rr < 8; rr++)
            #pragma unroll
            for (int c = 0; c < 12; c++) op[rr][c] = 0.f;

        #pragma unroll 2
        for (int e4 = 0; e4 < 48; e4++) {
            float oa[8][4];
            #pragma unroll
            for (int rr = 0; rr < 8; rr++) ld4(oa[rr], &OF[(ty * 8 + rr) * 196 + e4 * 4]);
            float wv[12][4];
            #pragma unroll
            for (int c = 0; c < 12; c++) ld4(wv[c], &o_w[(size_t)(tx * 12 + c) * DDIM + e4 * 4]);
            #pragma unroll
            for (int dd = 0; dd < 4; dd++)
                #pragma unroll
                for (int rr = 0; rr < 8; rr++)
                    #pragma unroll
                    for (int c = 0; c < 12; c++)
                        op[rr][c] += oa[rr][dd] * wv[c][dd];
        }

        #pragma unroll
        for (int rr = 0; rr < 8; rr++) {
            size_t off = (bN + q0 + ty * 8 + rr) * (size_t)DDIM + tx * 12;
            st4(&out[off],     &op[rr][0]);
            st4(&out[off + 4], &op[rr][4]);
            st4(&out[off + 8], &op[rr][8]);
        }
    }
}

// ---------------------------------------------------------------------------
// Kernel 3: normalize weights in place. All 4 loads issued before any store.
// ---------------------------------------------------------------------------
__global__ void norm_kernel(float* __restrict__ wout) {
    const int row = blockIdx.x;
    const float inv = 1.0f / g_Z[row];
    float4* p = reinterpret_cast<float4*>(wout) + (size_t)row * (NSEQ / 4);
    const int t = threadIdx.x;
    float4 v0 = p[t];
    float4 v1 = p[t + 256];
    float4 v2 = p[t + 512];
    float4 v3 = p[t + 768];
    v0.x *= inv; v0.y *= inv; v0.z *= inv; v0.w *= inv;
    v1.x *= inv; v1.y *= inv; v1.z *= inv; v1.w *= inv;
    v2.x *= inv; v2.y *= inv; v2.z *= inv; v2.w *= inv;
    v3.x *= inv; v3.y *= inv; v3.z *= inv; v3.w *= inv;
    p[t]       = v0;
    p[t + 256] = v1;
    p[t + 512] = v2;
    p[t + 768] = v3;
}

// ---------------------------------------------------------------------------
extern "C" void kernel_launch(void* const* d_in, const int* in_sizes, int n_in,
                              void* d_out, int out_size) {
    const float* query = (const float*)d_in[0];
    const float* key_t = (const float*)d_in[1];
    const float* value = (const float*)d_in[2];
    const float* mask  = (const float*)d_in[3];
    const float* bias  = (const float*)d_in[4];
    const float* q_w   = (const float*)d_in[5];
    const float* k_w   = (const float*)d_in[6];
    const float* v_w   = (const float*)d_in[7];
    const float* o_w   = (const float*)d_in[8];

    float* out  = (float*)d_out;
    float* wout = (float*)d_out + (size_t)BATCH * NSEQ * DDIM;

    cudaFuncSetAttribute(proj_kernel, cudaFuncAttributeMaxDynamicSharedMemorySize, PSMEM);
    cudaFuncSetAttribute(attn_kernel, cudaFuncAttributeMaxDynamicSharedMemorySize, ASMEM);

    const int TOT8 = (3 * BND + 3 * WSZ) / 8;
    convert_kernel<<<(TOT8 + 255) / 256, 256>>>(query, key_t, value, q_w, k_w, v_w);

    proj_kernel<<<148, 256, PSMEM>>>();

    dim3 agrid(NSEQ / 128, BATCH);
    attn_kernel<<<agrid, 256, ASMEM>>>(mask, bias, o_w, out, wout);

    norm_kernel<<<BATCH * NSEQ, 256>>>(wout);
}